// round 5
// baseline (speedup 1.0000x reference)
#include <cuda_runtime.h>
#include <math.h>

// Problem constants
#define NB    2
#define NRR   16384
#define MMSK  64
#define AD    128
#define HIDN  512
#define TOK   16          // tokens per block
#define NTHR  256

// Smem layout (float offsets)
#define OFF_Q    0        // 128
#define OFF_MB   128      // 64
#define OFF_ATT  192      // 256
#define OFF_RA   448      // 8
#define OFF_RB   456      // 8
#define OFF_AVP  464      // 256
#define OFF_XS   720      // 16*128 = 2048
#define OFF_XNT  2768     // 128*20 = 2560
#define OFF_A    5328     // max(K tile 64*128=8192, hdnT 512*20=10240) = 10240
#define OFF_B    15568    // max(V tile 8192, ypart 2*16*128=4096) = 8192
#define SMEM_FLOATS 23760
#define SMEM_BYTES  (SMEM_FLOATS * 4)

__device__ int g_mask_mode;   // 1 = 4-byte elements (int32/float32, nonzero==True), 0 = 1-byte

__global__ void detect_mask_kernel(const unsigned int* __restrict__ w) {
    int ok = 1;
    for (int i = threadIdx.x; i < 8192; i += NTHR) {   // 32KB scan, safe for any dtype
        unsigned int v = w[i];
        if (!(v == 0u || v == 1u || v == 0x3F800000u)) ok = 0;
    }
    int all = __syncthreads_and(ok);
    if (threadIdx.x == 0) g_mask_mode = all;
}

__device__ __forceinline__ float warp_sum(float v) {
    #pragma unroll
    for (int s = 16; s; s >>= 1) v += __shfl_xor_sync(0xffffffffu, v, s);
    return v;
}
__device__ __forceinline__ float warp_max(float v) {
    #pragma unroll
    for (int s = 16; s; s >>= 1) v = fmaxf(v, __shfl_xor_sync(0xffffffffu, v, s));
    return v;
}

__global__ __launch_bounds__(NTHR, 2)
void fused_bev_kernel(const float* __restrict__ Q,  const float* __restrict__ K,
                      const float* __restrict__ V,  const void*  __restrict__ maskp,
                      const float* __restrict__ g1, const float* __restrict__ be1,
                      const float* __restrict__ g2, const float* __restrict__ be2,
                      const float* __restrict__ W1, const float* __restrict__ bb1,
                      const float* __restrict__ W2, const float* __restrict__ bb2,
                      float* __restrict__ out)
{
    extern __shared__ float sm[];
    const int tid  = threadIdx.x;
    const int wid  = tid >> 5;
    const int lane = tid & 31;
    const int mode = g_mask_mode;

    float* qs   = sm + OFF_Q;
    float* mb   = sm + OFF_MB;
    float* att  = sm + OFF_ATT;
    float* ra   = sm + OFF_RA;
    float* rb   = sm + OFF_RB;
    float* avp  = sm + OFF_AVP;
    float* xs   = sm + OFF_XS;    // [16][128]  x = LN1(Q+attn) per token
    float* xnt  = sm + OFF_XNT;   // [128][20]  LN2(x) transposed (stride 20, f4-aligned)
    float* Ks   = sm + OFF_A;     // phase1: swizzled K tile
    float* hdnT = sm + OFF_A;     // phase2: [512][20]
    float* Vs   = sm + OFF_B;     // phase1: swizzled V tile
    float* yp   = sm + OFF_B;     // phase2: [2][16][128]

    const size_t gbase = (size_t)blockIdx.x * TOK;

    // ---------------- Phase 1: attention + LN1 + LN2 per token ----------------
    for (int t = 0; t < TOK; ++t) {
        const size_t g = gbase + (size_t)t;
        __syncthreads();

        // K/V tile load: contiguous 32KB each; store with 16B-unit rotation swizzle
        {
            const float4* Kg = (const float4*)(K + g * (size_t)(MMSK * AD));
            const float4* Vg = (const float4*)(V + g * (size_t)(MMSK * AD));
            #pragma unroll
            for (int r = 0; r < 8; ++r) {
                int idx = tid + r * NTHR;          // float4 index in [0,2048)
                int m = idx >> 5, c = idx & 31;
                int u = (c + m) & 31;
                *(float4*)(Ks + m * 128 + u * 4) = Kg[idx];
                *(float4*)(Vs + m * 128 + u * 4) = Vg[idx];
            }
            if (tid < 32) ((float4*)qs)[tid] = ((const float4*)(Q + g * AD))[tid];
            if (tid < MMSK) {
                int n = (int)(g % NRR);
                bool masked;
                if (mode) masked = ((const unsigned int*)maskp)[(size_t)n * MMSK + tid] != 0u;
                else      masked = ((const unsigned char*)maskp)[(size_t)n * MMSK + tid] != 0;
                mb[tid] = masked ? -INFINITY : 0.0f;
            }
        }
        __syncthreads();

        // logits: thread (h,m); swizzled float4 reads are conflict-free
        const int h = tid >> 6, m = tid & 63;
        float acc = 0.f;
        #pragma unroll
        for (int j4 = 0; j4 < 8; ++j4) {
            int u = (8 * h + j4 + m) & 31;
            float4 k4 = *(const float4*)(Ks + m * 128 + u * 4);
            float4 q4 = *(const float4*)(qs + (8 * h + j4) * 4);
            acc = fmaf(k4.x, q4.x, acc);
            acc = fmaf(k4.y, q4.y, acc);
            acc = fmaf(k4.z, q4.z, acc);
            acc = fmaf(k4.w, q4.w, acc);
        }
        float logit = acc * 0.17677669529663689f + mb[m];   // 1/sqrt(32), -inf if masked

        // softmax over 64 m (warps 2h, 2h+1)
        float wm = warp_max(logit);
        if (lane == 0) ra[wid] = wm;
        __syncthreads();
        float hmax = fmaxf(ra[2 * h], ra[2 * h + 1]);
        float p = __expf(logit - hmax);
        float ws = warp_sum(p);
        if (lane == 0) rb[wid] = ws;
        __syncthreads();
        float denom = rb[2 * h] + rb[2 * h + 1];
        att[tid] = p / denom;
        __syncthreads();

        // AV: thread (o, half) sums 32 m;  bank = (o + 4m) mod 32 -> conflict-free
        {
            int o = tid & 127, half = tid >> 7;
            int hh = o >> 5;
            const float* ah = att + hh * 64 + half * 32;
            float s = 0.f;
            #pragma unroll
            for (int i2 = 0; i2 < 32; ++i2) {
                int mm = half * 32 + i2;
                int u = (((o >> 2) + mm) & 31);
                s = fmaf(ah[i2], Vs[mm * 128 + u * 4 + (o & 3)], s);
            }
            avp[tid] = s;
        }
        __syncthreads();

        // residual + LN1 + LN2 (128 active threads, all 256 in barriers)
        const int o2 = tid & 127;
        float xv = 0.f;
        if (tid < 128) xv = qs[o2] + avp[o2] + avp[128 + o2];

        float v = (tid < 128) ? xv : 0.f;
        v = warp_sum(v);
        if (lane == 0) ra[wid] = v;
        __syncthreads();
        float mu = (ra[0]+ra[1]+ra[2]+ra[3]+ra[4]+ra[5]+ra[6]+ra[7]) * 0.0078125f;
        float dv = (tid < 128) ? (xv - mu) : 0.f;
        v = warp_sum(dv * dv);
        if (lane == 0) rb[wid] = v;
        __syncthreads();
        float var = (rb[0]+rb[1]+rb[2]+rb[3]+rb[4]+rb[5]+rb[6]+rb[7]) * 0.0078125f;
        float x1 = 0.f;
        if (tid < 128)
            x1 = dv * rsqrtf(var + 1e-5f) * __ldg(g1 + o2) + __ldg(be1 + o2);

        v = (tid < 128) ? x1 : 0.f;
        v = warp_sum(v);
        if (lane == 0) ra[wid] = v;
        __syncthreads();
        float mu2 = (ra[0]+ra[1]+ra[2]+ra[3]+ra[4]+ra[5]+ra[6]+ra[7]) * 0.0078125f;
        float dv2 = (tid < 128) ? (x1 - mu2) : 0.f;
        v = warp_sum(dv2 * dv2);
        if (lane == 0) rb[wid] = v;
        __syncthreads();
        float var2 = (rb[0]+rb[1]+rb[2]+rb[3]+rb[4]+rb[5]+rb[6]+rb[7]) * 0.0078125f;
        if (tid < 128) {
            float xn2 = dv2 * rsqrtf(var2 + 1e-5f) * __ldg(g2 + o2) + __ldg(be2 + o2);
            xs[t * 128 + o2]  = x1;
            xnt[o2 * 20 + t]  = xn2;
        }
    }
    __syncthreads();

    // ---------------- Phase 2: MLP for all 16 tokens ----------------
    // GEMM1: hdn[t][j] = gelu( sum_o xn2[t][o]*W1[o][j] + b1[j] )
    #pragma unroll
    for (int pass = 0; pass < 2; ++pass) {
        const int j = pass * 256 + tid;
        float a0=0,a1=0,a2=0,a3=0,a4=0,a5=0,a6=0,a7=0;
        float a8=0,a9=0,a10=0,a11=0,a12=0,a13=0,a14=0,a15=0;
        const float* w1p = W1 + j;
        #pragma unroll 2
        for (int oo = 0; oo < 128; ++oo) {
            float w = __ldg(w1p + oo * HIDN);
            const float4* xp = (const float4*)(xnt + oo * 20);
            float4 xa = xp[0], xb = xp[1], xc = xp[2], xd = xp[3];
            a0  = fmaf(xa.x, w, a0);  a1  = fmaf(xa.y, w, a1);
            a2  = fmaf(xa.z, w, a2);  a3  = fmaf(xa.w, w, a3);
            a4  = fmaf(xb.x, w, a4);  a5  = fmaf(xb.y, w, a5);
            a6  = fmaf(xb.z, w, a6);  a7  = fmaf(xb.w, w, a7);
            a8  = fmaf(xc.x, w, a8);  a9  = fmaf(xc.y, w, a9);
            a10 = fmaf(xc.z, w, a10); a11 = fmaf(xc.w, w, a11);
            a12 = fmaf(xd.x, w, a12); a13 = fmaf(xd.y, w, a13);
            a14 = fmaf(xd.z, w, a14); a15 = fmaf(xd.w, w, a15);
        }
        float bj = __ldg(bb1 + j);
        float accv[16] = {a0,a1,a2,a3,a4,a5,a6,a7,a8,a9,a10,a11,a12,a13,a14,a15};
        #pragma unroll
        for (int i = 0; i < 16; ++i) {
            float u = accv[i] + bj;
            hdnT[j * 20 + i] = 0.5f * u * (1.0f + erff(u * 0.7071067811865476f));
        }
    }
    __syncthreads();

    // GEMM2: y[t][o] = sum_j hdn[t][j]*W2[j][o]   (split j across thread halves)
    {
        const int o = tid & 127, jh = tid >> 7;
        float y0=0,y1=0,y2=0,y3=0,y4=0,y5=0,y6=0,y7=0;
        float y8=0,y9=0,y10=0,y11=0,y12=0,y13=0,y14=0,y15=0;
        const float* w2p = W2 + o;
        const int j0 = jh << 8;
        #pragma unroll 2
        for (int jj = 0; jj < 256; ++jj) {
            int j = j0 + jj;
            float w = __ldg(w2p + j * AD);
            const float4* hp = (const float4*)(hdnT + j * 20);
            float4 ha = hp[0], hb = hp[1], hc = hp[2], hd = hp[3];
            y0  = fmaf(ha.x, w, y0);  y1  = fmaf(ha.y, w, y1);
            y2  = fmaf(ha.z, w, y2);  y3  = fmaf(ha.w, w, y3);
            y4  = fmaf(hb.x, w, y4);  y5  = fmaf(hb.y, w, y5);
            y6  = fmaf(hb.z, w, y6);  y7  = fmaf(hb.w, w, y7);
            y8  = fmaf(hc.x, w, y8);  y9  = fmaf(hc.y, w, y9);
            y10 = fmaf(hc.z, w, y10); y11 = fmaf(hc.w, w, y11);
            y12 = fmaf(hd.x, w, y12); y13 = fmaf(hd.y, w, y13);
            y14 = fmaf(hd.z, w, y14); y15 = fmaf(hd.w, w, y15);
        }
        float yv[16] = {y0,y1,y2,y3,y4,y5,y6,y7,y8,y9,y10,y11,y12,y13,y14,y15};
        #pragma unroll
        for (int i = 0; i < 16; ++i)
            yp[(jh * 16 + i) * 128 + o] = yv[i];
    }
    __syncthreads();

    // combine + residual + b2 + store
    {
        const int o = tid & 127, tg = tid >> 7;
        float bv = __ldg(bb2 + o);
        #pragma unroll
        for (int i = 0; i < 8; ++i) {
            int t = tg * 8 + i;
            float val = yp[t * 128 + o] + yp[(16 + t) * 128 + o] + xs[t * 128 + o] + bv;
            out[(gbase + (size_t)t) * AD + o] = val;
        }
    }
}

extern "C" void kernel_launch(void* const* d_in, const int* in_sizes, int n_in,
                              void* d_out, int out_size)
{
    const float* Q   = (const float*)d_in[0];
    const float* K   = (const float*)d_in[1];
    const float* V   = (const float*)d_in[2];
    const void*  Mk  = d_in[3];
    const float* g1  = (const float*)d_in[4];
    const float* be1 = (const float*)d_in[5];
    const float* g2  = (const float*)d_in[6];
    const float* be2 = (const float*)d_in[7];
    const float* W1  = (const float*)d_in[8];
    const float* bb1 = (const float*)d_in[9];
    const float* W2  = (const float*)d_in[10];
    const float* bb2 = (const float*)d_in[11];
    float* out = (float*)d_out;

    cudaFuncSetAttribute(fused_bev_kernel,
                         cudaFuncAttributeMaxDynamicSharedMemorySize, SMEM_BYTES);

    detect_mask_kernel<<<1, NTHR>>>((const unsigned int*)Mk);

    const int nblocks = (NB * NRR) / TOK;   // 2048
    fused_bev_kernel<<<nblocks, NTHR, SMEM_BYTES>>>(
        Q, K, V, Mk, g1, be1, g2, be2, W1, bb1, W2, bb2, out);
}

// round 7
// speedup vs baseline: 1.6545x; 1.6545x over previous
#include <cuda_runtime.h>
#include <math.h>

// Problem constants
#define NB    2
#define NRR   16384
#define MMSK  64
#define AD    128
#define HIDN  512
#define TOK   16          // tokens per MLP block
#define NTHR  256
#define NTOK  (NB * NRR)  // 32768

__device__ int g_mask_mode;   // 1 = 4-byte elements (int32/float32), 0 = 1-byte (bool)
__device__ float g_x [NTOK * AD];   // LN1 output (residual for MLP)
__device__ float g_xn[NTOK * AD];   // LN2 output (MLP input)

__global__ void detect_mask_kernel(const unsigned int* __restrict__ w) {
    int ok = 1;
    for (int i = threadIdx.x; i < 8192; i += NTHR) {
        unsigned int v = w[i];
        if (!(v == 0u || v == 1u || v == 0x3F800000u)) ok = 0;
    }
    int all = __syncthreads_and(ok);
    if (threadIdx.x == 0) g_mask_mode = all;
}

__device__ __forceinline__ float warp_sum(float v) {
    #pragma unroll
    for (int s = 16; s; s >>= 1) v += __shfl_xor_sync(0xffffffffu, v, s);
    return v;
}
__device__ __forceinline__ float warp_max(float v) {
    #pragma unroll
    for (int s = 16; s; s >>= 1) v = fmaxf(v, __shfl_xor_sync(0xffffffffu, v, s));
    return v;
}

// ===================== Kernel A: attention + LN1 + LN2, one token per block =====================
// Smem floats: Ks 8192 | Vs 8192 | qs 128 | mb 64 | att 256 | ra 8 | rb 8 | avp 256 = 17104
#define A_SMEM_FLOATS 17104
#define A_SMEM_BYTES  (A_SMEM_FLOATS * 4)

__global__ __launch_bounds__(NTHR, 3)
void attn_kernel(const float* __restrict__ Q,  const float* __restrict__ K,
                 const float* __restrict__ V,  const void*  __restrict__ maskp,
                 const float* __restrict__ g1, const float* __restrict__ be1,
                 const float* __restrict__ g2, const float* __restrict__ be2)
{
    extern __shared__ float sm[];
    float* Ks  = sm;              // swizzled K tile
    float* Vs  = sm + 8192;       // swizzled V tile
    float* qs  = sm + 16384;
    float* mb  = sm + 16512;
    float* att = sm + 16576;
    float* ra  = sm + 16832;
    float* rb  = sm + 16840;
    float* avp = sm + 16848;

    const int tid  = threadIdx.x;
    const int wid  = tid >> 5;
    const int lane = tid & 31;
    const size_t g = (size_t)blockIdx.x;
    const int mode = g_mask_mode;

    // K/V tile via cp.async with 16B-unit rotation swizzle (c+m)&31
    {
        const float4* Kg = (const float4*)(K + g * (size_t)(MMSK * AD));
        const float4* Vg = (const float4*)(V + g * (size_t)(MMSK * AD));
        #pragma unroll
        for (int r = 0; r < 8; ++r) {
            int idx = tid + r * NTHR;          // float4 index in [0,2048)
            int m = idx >> 5, c = idx & 31;
            int u = (c + m) & 31;
            unsigned ka = (unsigned)__cvta_generic_to_shared(Ks + m * 128 + u * 4);
            unsigned va = (unsigned)__cvta_generic_to_shared(Vs + m * 128 + u * 4);
            asm volatile("cp.async.cg.shared.global [%0], [%1], 16;" :: "r"(ka), "l"(Kg + idx));
            asm volatile("cp.async.cg.shared.global [%0], [%1], 16;" :: "r"(va), "l"(Vg + idx));
        }
        asm volatile("cp.async.commit_group;");
        if (tid < 32) ((float4*)qs)[tid] = ((const float4*)(Q + g * AD))[tid];
        if (tid < MMSK) {
            int n = (int)(g % NRR);
            bool masked;
            if (mode) masked = ((const unsigned int*)maskp)[(size_t)n * MMSK + tid] != 0u;
            else      masked = ((const unsigned char*)maskp)[(size_t)n * MMSK + tid] != 0;
            mb[tid] = masked ? -INFINITY : 0.0f;
        }
        asm volatile("cp.async.wait_group 0;");
        __syncthreads();
    }

    // logits: thread (h,m); swizzled float4 reads are conflict-free
    const int h = tid >> 6, m = tid & 63;
    float acc = 0.f;
    #pragma unroll
    for (int j4 = 0; j4 < 8; ++j4) {
        int u = (8 * h + j4 + m) & 31;
        float4 k4 = *(const float4*)(Ks + m * 128 + u * 4);
        float4 q4 = *(const float4*)(qs + (8 * h + j4) * 4);
        acc = fmaf(k4.x, q4.x, acc);
        acc = fmaf(k4.y, q4.y, acc);
        acc = fmaf(k4.z, q4.z, acc);
        acc = fmaf(k4.w, q4.w, acc);
    }
    float logit = acc * 0.17677669529663689f + mb[m];   // 1/sqrt(32), -inf if masked

    // softmax over 64 m (warps 2h, 2h+1)
    float wm = warp_max(logit);
    if (lane == 0) ra[wid] = wm;
    __syncthreads();
    float hmax = fmaxf(ra[2 * h], ra[2 * h + 1]);
    float p = __expf(logit - hmax);
    float ws = warp_sum(p);
    if (lane == 0) rb[wid] = ws;
    __syncthreads();
    float denom = rb[2 * h] + rb[2 * h + 1];
    att[tid] = p / denom;
    __syncthreads();

    // AV: thread (o, half) sums 32 m; bank = (o + 4m) mod 32 -> conflict-free
    {
        int o = tid & 127, half = tid >> 7;
        int hh = o >> 5;
        const float* ah = att + hh * 64 + half * 32;
        float s = 0.f;
        #pragma unroll
        for (int i2 = 0; i2 < 32; ++i2) {
            int mm = half * 32 + i2;
            int u = (((o >> 2) + mm) & 31);
            s = fmaf(ah[i2], Vs[mm * 128 + u * 4 + (o & 3)], s);
        }
        avp[tid] = s;
    }
    __syncthreads();

    // residual + LN1 + LN2 (128 active threads, all 256 in barriers)
    const int o2 = tid & 127;
    float xv = 0.f;
    if (tid < 128) xv = qs[o2] + avp[o2] + avp[128 + o2];

    float v = (tid < 128) ? xv : 0.f;
    v = warp_sum(v);
    if (lane == 0) ra[wid] = v;
    __syncthreads();
    float mu = (ra[0]+ra[1]+ra[2]+ra[3]+ra[4]+ra[5]+ra[6]+ra[7]) * 0.0078125f;
    float dv = (tid < 128) ? (xv - mu) : 0.f;
    v = warp_sum(dv * dv);
    if (lane == 0) rb[wid] = v;
    __syncthreads();
    float var = (rb[0]+rb[1]+rb[2]+rb[3]+rb[4]+rb[5]+rb[6]+rb[7]) * 0.0078125f;
    float x1 = 0.f;
    if (tid < 128)
        x1 = dv * rsqrtf(var + 1e-5f) * __ldg(g1 + o2) + __ldg(be1 + o2);

    v = (tid < 128) ? x1 : 0.f;
    v = warp_sum(v);
    if (lane == 0) ra[wid] = v;
    __syncthreads();
    float mu2 = (ra[0]+ra[1]+ra[2]+ra[3]+ra[4]+ra[5]+ra[6]+ra[7]) * 0.0078125f;
    float dv2 = (tid < 128) ? (x1 - mu2) : 0.f;
    v = warp_sum(dv2 * dv2);
    if (lane == 0) rb[wid] = v;
    __syncthreads();
    float var2 = (rb[0]+rb[1]+rb[2]+rb[3]+rb[4]+rb[5]+rb[6]+rb[7]) * 0.0078125f;
    if (tid < 128) {
        float xn2 = dv2 * rsqrtf(var2 + 1e-5f) * __ldg(g2 + o2) + __ldg(be2 + o2);
        g_x [g * AD + o2] = x1;
        g_xn[g * AD + o2] = xn2;
    }
}

// ===================== Kernel B: MLP for 16 tokens per block =====================
// Smem floats: xs 2048 | xnt 2560 | hdnT 10240 (yp[2][16][128]=4096 overlays hdnT) = 14848
#define B_SMEM_FLOATS 14848
#define B_SMEM_BYTES  (B_SMEM_FLOATS * 4)

__global__ __launch_bounds__(NTHR, 2)
void mlp_kernel(const float* __restrict__ W1, const float* __restrict__ bb1,
                const float* __restrict__ W2, const float* __restrict__ bb2,
                float* __restrict__ out)
{
    extern __shared__ float sm[];
    float* xs   = sm;            // [16][128] residual x
    float* xnt  = sm + 2048;     // [128][20] LN2(x) transposed
    float* hdnT = sm + 4608;     // [512][20]
    float* yp   = sm + 4608;     // [2][16][128] overlays hdnT after sync

    const int tid = threadIdx.x;
    const size_t gbase = (size_t)blockIdx.x * TOK;

    // load + transpose
    for (int i = tid; i < TOK * AD; i += NTHR) {
        int t = i >> 7, o = i & 127;
        float xv  = g_x [(gbase + t) * AD + o];
        float xnv = g_xn[(gbase + t) * AD + o];
        xs[i] = xv;
        xnt[o * 20 + t] = xnv;
    }
    __syncthreads();

    // GEMM1: hdn[t][j] = gelu( sum_o xn2[t][o]*W1[o][j] + b1[j] )
    #pragma unroll
    for (int pass = 0; pass < 2; ++pass) {
        const int j = pass * 256 + tid;
        float a0=0,a1=0,a2=0,a3=0,a4=0,a5=0,a6=0,a7=0;
        float a8=0,a9=0,a10=0,a11=0,a12=0,a13=0,a14=0,a15=0;
        const float* w1p = W1 + j;
        #pragma unroll 2
        for (int oo = 0; oo < 128; ++oo) {
            float w = __ldg(w1p + oo * HIDN);
            const float4* xp = (const float4*)(xnt + oo * 20);
            float4 xa = xp[0], xb = xp[1], xc = xp[2], xd = xp[3];
            a0  = fmaf(xa.x, w, a0);  a1  = fmaf(xa.y, w, a1);
            a2  = fmaf(xa.z, w, a2);  a3  = fmaf(xa.w, w, a3);
            a4  = fmaf(xb.x, w, a4);  a5  = fmaf(xb.y, w, a5);
            a6  = fmaf(xb.z, w, a6);  a7  = fmaf(xb.w, w, a7);
            a8  = fmaf(xc.x, w, a8);  a9  = fmaf(xc.y, w, a9);
            a10 = fmaf(xc.z, w, a10); a11 = fmaf(xc.w, w, a11);
            a12 = fmaf(xd.x, w, a12); a13 = fmaf(xd.y, w, a13);
            a14 = fmaf(xd.z, w, a14); a15 = fmaf(xd.w, w, a15);
        }
        float bj = __ldg(bb1 + j);
        float accv[16] = {a0,a1,a2,a3,a4,a5,a6,a7,a8,a9,a10,a11,a12,a13,a14,a15};
        #pragma unroll
        for (int i = 0; i < 16; ++i) {
            float u = accv[i] + bj;
            hdnT[j * 20 + i] = 0.5f * u * (1.0f + erff(u * 0.7071067811865476f));
        }
    }
    __syncthreads();

    // GEMM2: y[t][o] = sum_j hdn[t][j]*W2[j][o]  (split j across thread halves)
    {
        const int o = tid & 127, jh = tid >> 7;
        float y0=0,y1=0,y2=0,y3=0,y4=0,y5=0,y6=0,y7=0;
        float y8=0,y9=0,y10=0,y11=0,y12=0,y13=0,y14=0,y15=0;
        const float* w2p = W2 + o;
        const int j0 = jh << 8;
        #pragma unroll 2
        for (int jj = 0; jj < 256; ++jj) {
            int j = j0 + jj;
            float w = __ldg(w2p + j * AD);
            const float4* hp = (const float4*)(hdnT + j * 20);
            float4 ha = hp[0], hb = hp[1], hc = hp[2], hd = hp[3];
            y0  = fmaf(ha.x, w, y0);  y1  = fmaf(ha.y, w, y1);
            y2  = fmaf(ha.z, w, y2);  y3  = fmaf(ha.w, w, y3);
            y4  = fmaf(hb.x, w, y4);  y5  = fmaf(hb.y, w, y5);
            y6  = fmaf(hb.z, w, y6);  y7  = fmaf(hb.w, w, y7);
            y8  = fmaf(hc.x, w, y8);  y9  = fmaf(hc.y, w, y9);
            y10 = fmaf(hc.z, w, y10); y11 = fmaf(hc.w, w, y11);
            y12 = fmaf(hd.x, w, y12); y13 = fmaf(hd.y, w, y13);
            y14 = fmaf(hd.z, w, y14); y15 = fmaf(hd.w, w, y15);
        }
        float yv[16] = {y0,y1,y2,y3,y4,y5,y6,y7,y8,y9,y10,y11,y12,y13,y14,y15};
        __syncthreads();   // all reads of hdnT complete before yp overlays it
        #pragma unroll
        for (int i = 0; i < 16; ++i)
            yp[(jh * 16 + i) * 128 + o] = yv[i];
    }
    __syncthreads();

    // combine + residual + b2 + store
    {
        const int o = tid & 127, tg = tid >> 7;
        float bv = __ldg(bb2 + o);
        #pragma unroll
        for (int i = 0; i < 8; ++i) {
            int t = tg * 8 + i;
            float val = yp[t * 128 + o] + yp[(16 + t) * 128 + o] + xs[t * 128 + o] + bv;
            out[(gbase + (size_t)t) * AD + o] = val;
        }
    }
}

extern "C" void kernel_launch(void* const* d_in, const int* in_sizes, int n_in,
                              void* d_out, int out_size)
{
    const float* Q   = (const float*)d_in[0];
    const float* K   = (const float*)d_in[1];
    const float* V   = (const float*)d_in[2];
    const void*  Mk  = d_in[3];
    const float* g1  = (const float*)d_in[4];
    const float* be1 = (const float*)d_in[5];
    const float* g2  = (const float*)d_in[6];
    const float* be2 = (const float*)d_in[7];
    const float* W1  = (const float*)d_in[8];
    const float* bb1 = (const float*)d_in[9];
    const float* W2  = (const float*)d_in[10];
    const float* bb2 = (const float*)d_in[11];
    float* out = (float*)d_out;

    cudaFuncSetAttribute(attn_kernel,
                         cudaFuncAttributeMaxDynamicSharedMemorySize, A_SMEM_BYTES);
    cudaFuncSetAttribute(mlp_kernel,
                         cudaFuncAttributeMaxDynamicSharedMemorySize, B_SMEM_BYTES);

    detect_mask_kernel<<<1, NTHR>>>((const unsigned int*)Mk);

    attn_kernel<<<NTOK, NTHR, A_SMEM_BYTES>>>(Q, K, V, Mk, g1, be1, g2, be2);

    mlp_kernel<<<NTOK / TOK, NTHR, B_SMEM_BYTES>>>(W1, bb1, W2, bb2, out);
}

// round 8
// speedup vs baseline: 1.7564x; 1.0616x over previous
#include <cuda_runtime.h>
#include <math.h>

// Problem constants
#define NB    2
#define NRR   16384
#define MMSK  64
#define AD    128
#define HIDN  512
#define TOK   16          // tokens per MLP block
#define NTHR  256
#define NTOK  (NB * NRR)  // 32768

typedef unsigned long long ull;

__device__ int g_mask_mode;   // 1 = 4-byte elements (int32/float32), 0 = 1-byte (bool)
__device__ float g_x [NTOK * AD];   // LN1 output (residual for MLP)
__device__ float g_xn[NTOK * AD];   // LN2 output (MLP input)

__global__ void detect_mask_kernel(const unsigned int* __restrict__ w) {
    int ok = 1;
    for (int i = threadIdx.x; i < 8192; i += 1024) {
        unsigned int v = w[i];
        if (!(v == 0u || v == 1u || v == 0x3F800000u)) ok = 0;
    }
    int all = __syncthreads_and(ok);
    if (threadIdx.x == 0) g_mask_mode = all;
}

__device__ __forceinline__ float warp_sum(float v) {
    #pragma unroll
    for (int s = 16; s; s >>= 1) v += __shfl_xor_sync(0xffffffffu, v, s);
    return v;
}
__device__ __forceinline__ float warp_max(float v) {
    #pragma unroll
    for (int s = 16; s; s >>= 1) v = fmaxf(v, __shfl_xor_sync(0xffffffffu, v, s));
    return v;
}

// packed f32x2 helpers (Blackwell FFMA2 — PTX-only path)
__device__ __forceinline__ ull pack2(float lo, float hi) {
    ull r; asm("mov.b64 %0, {%1, %2};" : "=l"(r) : "f"(lo), "f"(hi)); return r;
}
__device__ __forceinline__ void unpack2(ull v, float& lo, float& hi) {
    asm("mov.b64 {%0, %1}, %2;" : "=f"(lo), "=f"(hi) : "l"(v));
}
#define FFMA2(d, a, b, c) asm("fma.rn.f32x2 %0, %1, %2, %3;" : "=l"(d) : "l"(a), "l"(b), "l"(c))

// ===================== Kernel A: attention + LN1 + LN2, one token per block =====================
// Smem floats: Ks 8192 | Vs 8192 | qs 128 | mb 64 | att 256 | ra/rb/rc/rd 4x8 | avp 256 = 17128
#define A_SMEM_FLOATS 17136
#define A_SMEM_BYTES  (A_SMEM_FLOATS * 4)

__global__ __launch_bounds__(NTHR, 3)
void attn_kernel(const float* __restrict__ Q,  const float* __restrict__ K,
                 const float* __restrict__ V,  const void*  __restrict__ maskp,
                 const float* __restrict__ g1, const float* __restrict__ be1,
                 const float* __restrict__ g2, const float* __restrict__ be2)
{
    extern __shared__ float sm[];
    float* Ks  = sm;              // swizzled K tile
    float* Vs  = sm + 8192;       // swizzled V tile
    float* qs  = sm + 16384;
    float* mb  = sm + 16512;
    float* att = sm + 16576;
    float* ra  = sm + 16832;
    float* rb  = sm + 16840;
    float* rc  = sm + 16848;
    float* rd  = sm + 16856;
    float* avp = sm + 16864;

    const int tid  = threadIdx.x;
    const int wid  = tid >> 5;
    const int lane = tid & 31;
    const size_t g = (size_t)blockIdx.x;
    const int mode = g_mask_mode;

    // K/V tile via cp.async with 16B-unit rotation swizzle (c+m)&31
    {
        const float4* Kg = (const float4*)(K + g * (size_t)(MMSK * AD));
        const float4* Vg = (const float4*)(V + g * (size_t)(MMSK * AD));
        #pragma unroll
        for (int r = 0; r < 8; ++r) {
            int idx = tid + r * NTHR;          // float4 index in [0,2048)
            int m = idx >> 5, c = idx & 31;
            int u = (c + m) & 31;
            unsigned ka = (unsigned)__cvta_generic_to_shared(Ks + m * 128 + u * 4);
            unsigned va = (unsigned)__cvta_generic_to_shared(Vs + m * 128 + u * 4);
            asm volatile("cp.async.cg.shared.global [%0], [%1], 16;" :: "r"(ka), "l"(Kg + idx));
            asm volatile("cp.async.cg.shared.global [%0], [%1], 16;" :: "r"(va), "l"(Vg + idx));
        }
        asm volatile("cp.async.commit_group;");
        if (tid < 32) ((float4*)qs)[tid] = ((const float4*)(Q + g * AD))[tid];
        if (tid < MMSK) {
            int n = (int)(g % NRR);
            bool masked;
            if (mode) masked = ((const unsigned int*)maskp)[(size_t)n * MMSK + tid] != 0u;
            else      masked = ((const unsigned char*)maskp)[(size_t)n * MMSK + tid] != 0;
            mb[tid] = masked ? -INFINITY : 0.0f;
        }
        asm volatile("cp.async.wait_group 0;");
        __syncthreads();                                                // BAR 1
    }

    // logits + softmax: warp w = head w (warps 0-3), lane owns m=lane and m=lane+32.
    // Softmax entirely warp-local: no cross-warp combine, no barriers.
    if (wid < 4) {
        const int h = wid;
        const int m0 = lane, m1 = lane + 32;
        float acc0 = 0.f, acc1 = 0.f;
        #pragma unroll
        for (int j4 = 0; j4 < 8; ++j4) {
            int c = 8 * h + j4;
            float4 q4 = *(const float4*)(qs + c * 4);
            int u0 = (c + m0) & 31;
            float4 k0 = *(const float4*)(Ks + m0 * 128 + u0 * 4);
            acc0 = fmaf(k0.x, q4.x, acc0); acc0 = fmaf(k0.y, q4.y, acc0);
            acc0 = fmaf(k0.z, q4.z, acc0); acc0 = fmaf(k0.w, q4.w, acc0);
            int u1 = (c + m1) & 31;
            float4 k1 = *(const float4*)(Ks + m1 * 128 + u1 * 4);
            acc1 = fmaf(k1.x, q4.x, acc1); acc1 = fmaf(k1.y, q4.y, acc1);
            acc1 = fmaf(k1.z, q4.z, acc1); acc1 = fmaf(k1.w, q4.w, acc1);
        }
        float l0 = acc0 * 0.17677669529663689f + mb[m0];   // 1/sqrt(32)
        float l1 = acc1 * 0.17677669529663689f + mb[m1];
        float wm = warp_max(fmaxf(l0, l1));
        float p0 = __expf(l0 - wm), p1 = __expf(l1 - wm);
        float s  = warp_sum(p0 + p1);
        float inv = 1.0f / s;
        att[h * 64 + m0] = p0 * inv;
        att[h * 64 + m1] = p1 * inv;
    }
    __syncthreads();                                                    // BAR 2

    // AV: thread (o, half) sums 32 m; bank = (o + 4m) mod 32 -> conflict-free
    {
        int o = tid & 127, half = tid >> 7;
        int hh = o >> 5;
        const float* ah = att + hh * 64 + half * 32;
        float s = 0.f;
        #pragma unroll
        for (int i2 = 0; i2 < 32; ++i2) {
            int mm = half * 32 + i2;
            int u = (((o >> 2) + mm) & 31);
            s = fmaf(ah[i2], Vs[mm * 128 + u * 4 + (o & 3)], s);
        }
        avp[tid] = s;
    }
    __syncthreads();                                                    // BAR 3

    // residual + LN1 + LN2 via single-pass E[x^2]-E[x]^2 (2 reduction rounds total)
    const int o2 = tid & 127;
    float xv = 0.f;
    if (tid < 128) xv = qs[o2] + avp[o2] + avp[128 + o2];

    {
        float s1 = warp_sum((tid < 128) ? xv : 0.f);
        float s2 = warp_sum((tid < 128) ? xv * xv : 0.f);
        if (lane == 0 && wid < 4) { ra[wid] = s1; rb[wid] = s2; }
    }
    __syncthreads();                                                    // BAR 4
    float mu  = (ra[0] + ra[1] + ra[2] + ra[3]) * 0.0078125f;
    float ex2 = (rb[0] + rb[1] + rb[2] + rb[3]) * 0.0078125f;
    float var = ex2 - mu * mu;
    float x1 = 0.f;
    if (tid < 128)
        x1 = (xv - mu) * rsqrtf(var + 1e-5f) * __ldg(g1 + o2) + __ldg(be1 + o2);

    {
        float s1 = warp_sum((tid < 128) ? x1 : 0.f);
        float s2 = warp_sum((tid < 128) ? x1 * x1 : 0.f);
        if (lane == 0 && wid < 4) { rc[wid] = s1; rd[wid] = s2; }
    }
    __syncthreads();                                                    // BAR 5
    float mu2  = (rc[0] + rc[1] + rc[2] + rc[3]) * 0.0078125f;
    float ex22 = (rd[0] + rd[1] + rd[2] + rd[3]) * 0.0078125f;
    float var2 = ex22 - mu2 * mu2;
    if (tid < 128) {
        float xn2 = (x1 - mu2) * rsqrtf(var2 + 1e-5f) * __ldg(g2 + o2) + __ldg(be2 + o2);
        g_x [g * AD + o2] = x1;
        g_xn[g * AD + o2] = xn2;
    }
}

// ===================== Kernel B: MLP for 16 tokens per block (packed f32x2) =====================
// Smem floats: xs 2048 | xnt 2560 | hdnT 10240 (yp[2][16][128]=4096 overlays hdnT) = 14848
#define B_SMEM_FLOATS 14848
#define B_SMEM_BYTES  (B_SMEM_FLOATS * 4)

__global__ __launch_bounds__(NTHR, 2)
void mlp_kernel(const float* __restrict__ W1, const float* __restrict__ bb1,
                const float* __restrict__ W2, const float* __restrict__ bb2,
                float* __restrict__ out)
{
    extern __shared__ float sm[];
    float* xs   = sm;            // [16][128] residual x
    float* xnt  = sm + 2048;     // [128][20] LN2(x) transposed (16B-aligned rows)
    float* hdnT = sm + 4608;     // [512][20]
    float* yp   = sm + 4608;     // [2][16][128] overlays hdnT after sync

    const int tid = threadIdx.x;
    const size_t gbase = (size_t)blockIdx.x * TOK;

    // load + transpose
    for (int i = tid; i < TOK * AD; i += NTHR) {
        int t = i >> 7, o = i & 127;
        xs[i] = g_x [(gbase + t) * AD + o];
        xnt[o * 20 + t] = g_xn[(gbase + t) * AD + o];
    }
    __syncthreads();

    // GEMM1: hdn[t][j] = gelu( sum_o xn2[t][o]*W1[o][j] + b1[j] )  -- f32x2, tokens paired
    #pragma unroll
    for (int pass = 0; pass < 2; ++pass) {
        const int j = pass * 256 + tid;
        ull A0=0,A1=0,A2=0,A3=0,A4=0,A5=0,A6=0,A7=0;
        const float* w1p = W1 + j;
        #pragma unroll 2
        for (int oo = 0; oo < 128; ++oo) {
            float w = __ldg(w1p + oo * HIDN);
            ull wp = pack2(w, w);
            const ulonglong2* xp = (const ulonglong2*)(xnt + oo * 20);
            ulonglong2 p0 = xp[0], p1 = xp[1], p2 = xp[2], p3 = xp[3];
            FFMA2(A0, p0.x, wp, A0); FFMA2(A1, p0.y, wp, A1);
            FFMA2(A2, p1.x, wp, A2); FFMA2(A3, p1.y, wp, A3);
            FFMA2(A4, p2.x, wp, A4); FFMA2(A5, p2.y, wp, A5);
            FFMA2(A6, p3.x, wp, A6); FFMA2(A7, p3.y, wp, A7);
        }
        float bj = __ldg(bb1 + j);
        ull Av[8] = {A0,A1,A2,A3,A4,A5,A6,A7};
        #pragma unroll
        for (int q = 0; q < 8; ++q) {
            float lo, hi; unpack2(Av[q], lo, hi);
            float u0 = lo + bj, u1 = hi + bj;
            hdnT[j * 20 + 2 * q    ] = 0.5f * u0 * (1.0f + erff(u0 * 0.7071067811865476f));
            hdnT[j * 20 + 2 * q + 1] = 0.5f * u1 * (1.0f + erff(u1 * 0.7071067811865476f));
        }
    }
    __syncthreads();

    // GEMM2: y[t][o] = sum_j hdn[t][j]*W2[j][o]  (split j across thread halves) -- f32x2
    {
        const int o = tid & 127, jh = tid >> 7;
        ull Y0=0,Y1=0,Y2=0,Y3=0,Y4=0,Y5=0,Y6=0,Y7=0;
        const float* w2p = W2 + o;
        const int j0 = jh << 8;
        #pragma unroll 2
        for (int jj = 0; jj < 256; ++jj) {
            int jx = j0 + jj;
            float w = __ldg(w2p + jx * AD);
            ull wp = pack2(w, w);
            const ulonglong2* hp = (const ulonglong2*)(hdnT + jx * 20);
            ulonglong2 p0 = hp[0], p1 = hp[1], p2 = hp[2], p3 = hp[3];
            FFMA2(Y0, p0.x, wp, Y0); FFMA2(Y1, p0.y, wp, Y1);
            FFMA2(Y2, p1.x, wp, Y2); FFMA2(Y3, p1.y, wp, Y3);
            FFMA2(Y4, p2.x, wp, Y4); FFMA2(Y5, p2.y, wp, Y5);
            FFMA2(Y6, p3.x, wp, Y6); FFMA2(Y7, p3.y, wp, Y7);
        }
        ull Yv[8] = {Y0,Y1,Y2,Y3,Y4,Y5,Y6,Y7};
        float yv[16];
        #pragma unroll
        for (int q = 0; q < 8; ++q) unpack2(Yv[q], yv[2 * q], yv[2 * q + 1]);
        __syncthreads();   // all reads of hdnT complete before yp overlays it
        #pragma unroll
        for (int i = 0; i < 16; ++i)
            yp[(jh * 16 + i) * 128 + o] = yv[i];
    }
    __syncthreads();

    // combine + residual + b2 + store
    {
        const int o = tid & 127, tg = tid >> 7;
        float bv = __ldg(bb2 + o);
        #pragma unroll
        for (int i = 0; i < 8; ++i) {
            int t = tg * 8 + i;
            float val = yp[t * 128 + o] + yp[(16 + t) * 128 + o] + xs[t * 128 + o] + bv;
            out[(gbase + (size_t)t) * AD + o] = val;
        }
    }
}

extern "C" void kernel_launch(void* const* d_in, const int* in_sizes, int n_in,
                              void* d_out, int out_size)
{
    const float* Q   = (const float*)d_in[0];
    const float* K   = (const float*)d_in[1];
    const float* V   = (const float*)d_in[2];
    const void*  Mk  = d_in[3];
    const float* g1  = (const float*)d_in[4];
    const float* be1 = (const float*)d_in[5];
    const float* g2  = (const float*)d_in[6];
    const float* be2 = (const float*)d_in[7];
    const float* W1  = (const float*)d_in[8];
    const float* bb1 = (const float*)d_in[9];
    const float* W2  = (const float*)d_in[10];
    const float* bb2 = (const float*)d_in[11];
    float* out = (float*)d_out;

    cudaFuncSetAttribute(attn_kernel,
                         cudaFuncAttributeMaxDynamicSharedMemorySize, A_SMEM_BYTES);
    cudaFuncSetAttribute(mlp_kernel,
                         cudaFuncAttributeMaxDynamicSharedMemorySize, B_SMEM_BYTES);

    detect_mask_kernel<<<1, 1024>>>((const unsigned int*)Mk);

    attn_kernel<<<NTOK, NTHR, A_SMEM_BYTES>>>(Q, K, V, Mk, g1, be1, g2, be2);

    mlp_kernel<<<NTOK / TOK, NTHR, B_SMEM_BYTES>>>(W1, bb1, W2, bb2, out);
}

// round 9
// speedup vs baseline: 1.8654x; 1.0621x over previous
#include <cuda_runtime.h>
#include <math.h>

// Problem constants
#define NB    2
#define NRR   16384
#define MMSK  64
#define AD    128
#define HIDN  512
#define TOK   16          // tokens per MLP block
#define NTHR  256
#define NTOK  (NB * NRR)  // 32768

typedef unsigned long long ull;

__device__ int g_mask_mode;   // 1 = 4-byte elements (int32/float32), 0 = 1-byte (bool)
__device__ float g_x [NTOK * AD];   // LN1 output (residual for MLP)
__device__ float g_xn[NTOK * AD];   // LN2 output (MLP input)

__global__ void detect_mask_kernel(const unsigned int* __restrict__ w) {
    int ok = 1;
    for (int i = threadIdx.x; i < 2048; i += NTHR) {
        unsigned int v = w[i];
        if (!(v == 0u || v == 1u || v == 0x3F800000u)) ok = 0;
    }
    int all = __syncthreads_and(ok);
    if (threadIdx.x == 0) g_mask_mode = all;
}

__global__ void pad_kernel() {}   // aligns ncu -s 5 capture onto attn_kernel

__device__ __forceinline__ float warp_sum(float v) {
    #pragma unroll
    for (int s = 16; s; s >>= 1) v += __shfl_xor_sync(0xffffffffu, v, s);
    return v;
}
__device__ __forceinline__ float warp_max(float v) {
    #pragma unroll
    for (int s = 16; s; s >>= 1) v = fmaxf(v, __shfl_xor_sync(0xffffffffu, v, s));
    return v;
}

// packed f32x2 helpers (Blackwell FFMA2 — PTX-only path)
__device__ __forceinline__ ull pack2(float lo, float hi) {
    ull r; asm("mov.b64 %0, {%1, %2};" : "=l"(r) : "f"(lo), "f"(hi)); return r;
}
__device__ __forceinline__ void unpack2(ull v, float& lo, float& hi) {
    asm("mov.b64 {%0, %1}, %2;" : "=f"(lo), "=f"(hi) : "l"(v));
}
#define FFMA2(d, a, b, c) asm("fma.rn.f32x2 %0, %1, %2, %3;" : "=l"(d) : "l"(a), "l"(b), "l"(c))

// ===================== Kernel A: attention + LN1 + LN2, one token per block =====================
// Smem floats: Ks 8192 | Vs 8192 | qs 128 | mb 64 | att 256 | ra/rb/rc/rd 4x8 | avp 256
#define A_SMEM_FLOATS 17136
#define A_SMEM_BYTES  (A_SMEM_FLOATS * 4)

__global__ __launch_bounds__(NTHR, 3)
void attn_kernel(const float* __restrict__ Q,  const float* __restrict__ K,
                 const float* __restrict__ V,  const void*  __restrict__ maskp,
                 const float* __restrict__ g1, const float* __restrict__ be1,
                 const float* __restrict__ g2, const float* __restrict__ be2)
{
    extern __shared__ float sm[];
    float* Ks  = sm;              // swizzled K tile
    float* Vs  = sm + 8192;       // swizzled V tile
    float* qs  = sm + 16384;
    float* mb  = sm + 16512;
    float* att = sm + 16576;
    float* ra  = sm + 16832;
    float* rb  = sm + 16840;
    float* rc  = sm + 16848;
    float* rd  = sm + 16856;
    float* avp = sm + 16864;

    const int tid  = threadIdx.x;
    const int wid  = tid >> 5;
    const int lane = tid & 31;
    const size_t g = (size_t)blockIdx.x;
    const int mode = g_mask_mode;

    // K group first, V second -> V load overlaps logits+softmax
    {
        const float4* Kg = (const float4*)(K + g * (size_t)(MMSK * AD));
        const float4* Vg = (const float4*)(V + g * (size_t)(MMSK * AD));
        #pragma unroll
        for (int r = 0; r < 8; ++r) {
            int idx = tid + r * NTHR;          // float4 index in [0,2048)
            int m = idx >> 5, c = idx & 31;
            int u = (c + m) & 31;
            unsigned ka = (unsigned)__cvta_generic_to_shared(Ks + m * 128 + u * 4);
            asm volatile("cp.async.cg.shared.global [%0], [%1], 16;" :: "r"(ka), "l"(Kg + idx));
        }
        asm volatile("cp.async.commit_group;");        // group: K
        #pragma unroll
        for (int r = 0; r < 8; ++r) {
            int idx = tid + r * NTHR;
            int m = idx >> 5, c = idx & 31;
            int u = (c + m) & 31;
            unsigned va = (unsigned)__cvta_generic_to_shared(Vs + m * 128 + u * 4);
            asm volatile("cp.async.cg.shared.global [%0], [%1], 16;" :: "r"(va), "l"(Vg + idx));
        }
        asm volatile("cp.async.commit_group;");        // group: V
        if (tid < 32) ((float4*)qs)[tid] = ((const float4*)(Q + g * AD))[tid];
        if (tid < MMSK) {
            int n = (int)(g % NRR);
            bool masked;
            if (mode) masked = ((const unsigned int*)maskp)[(size_t)n * MMSK + tid] != 0u;
            else      masked = ((const unsigned char*)maskp)[(size_t)n * MMSK + tid] != 0;
            mb[tid] = masked ? -INFINITY : 0.0f;
        }
        asm volatile("cp.async.wait_group 1;");        // K complete (V may be in flight)
        __syncthreads();                                                // BAR 1
    }

    // logits + softmax: warp w = head w (warps 0-3), lane owns m=lane and m=lane+32.
    if (wid < 4) {
        const int h = wid;
        const int m0 = lane, m1 = lane + 32;
        float acc0 = 0.f, acc1 = 0.f;
        #pragma unroll
        for (int j4 = 0; j4 < 8; ++j4) {
            int c = 8 * h + j4;
            float4 q4 = *(const float4*)(qs + c * 4);
            int u0 = (c + m0) & 31;
            float4 k0 = *(const float4*)(Ks + m0 * 128 + u0 * 4);
            acc0 = fmaf(k0.x, q4.x, acc0); acc0 = fmaf(k0.y, q4.y, acc0);
            acc0 = fmaf(k0.z, q4.z, acc0); acc0 = fmaf(k0.w, q4.w, acc0);
            int u1 = (c + m1) & 31;
            float4 k1 = *(const float4*)(Ks + m1 * 128 + u1 * 4);
            acc1 = fmaf(k1.x, q4.x, acc1); acc1 = fmaf(k1.y, q4.y, acc1);
            acc1 = fmaf(k1.z, q4.z, acc1); acc1 = fmaf(k1.w, q4.w, acc1);
        }
        float l0 = acc0 * 0.17677669529663689f + mb[m0];   // 1/sqrt(32)
        float l1 = acc1 * 0.17677669529663689f + mb[m1];
        float wm = warp_max(fmaxf(l0, l1));
        float p0 = __expf(l0 - wm), p1 = __expf(l1 - wm);
        float s  = warp_sum(p0 + p1);
        float inv = 1.0f / s;
        att[h * 64 + m0] = p0 * inv;
        att[h * 64 + m1] = p1 * inv;
    }
    asm volatile("cp.async.wait_group 0;");            // V complete
    __syncthreads();                                                    // BAR 2

    // AV: thread (o, half) sums 32 m; bank = (o + 4m) mod 32 -> conflict-free
    {
        int o = tid & 127, half = tid >> 7;
        int hh = o >> 5;
        const float* ah = att + hh * 64 + half * 32;
        float s = 0.f;
        #pragma unroll
        for (int i2 = 0; i2 < 32; ++i2) {
            int mm = half * 32 + i2;
            int u = (((o >> 2) + mm) & 31);
            s = fmaf(ah[i2], Vs[mm * 128 + u * 4 + (o & 3)], s);
        }
        avp[tid] = s;
    }
    __syncthreads();                                                    // BAR 3

    // residual + LN1 + LN2 via single-pass E[x^2]-E[x]^2
    const int o2 = tid & 127;
    float xv = 0.f;
    if (tid < 128) xv = qs[o2] + avp[o2] + avp[128 + o2];

    {
        float s1 = warp_sum((tid < 128) ? xv : 0.f);
        float s2 = warp_sum((tid < 128) ? xv * xv : 0.f);
        if (lane == 0 && wid < 4) { ra[wid] = s1; rb[wid] = s2; }
    }
    __syncthreads();                                                    // BAR 4
    float mu  = (ra[0] + ra[1] + ra[2] + ra[3]) * 0.0078125f;
    float ex2 = (rb[0] + rb[1] + rb[2] + rb[3]) * 0.0078125f;
    float var = ex2 - mu * mu;
    float x1 = 0.f;
    if (tid < 128)
        x1 = (xv - mu) * rsqrtf(var + 1e-5f) * __ldg(g1 + o2) + __ldg(be1 + o2);

    {
        float s1 = warp_sum((tid < 128) ? x1 : 0.f);
        float s2 = warp_sum((tid < 128) ? x1 * x1 : 0.f);
        if (lane == 0 && wid < 4) { rc[wid] = s1; rd[wid] = s2; }
    }
    __syncthreads();                                                    // BAR 5
    float mu2  = (rc[0] + rc[1] + rc[2] + rc[3]) * 0.0078125f;
    float ex22 = (rd[0] + rd[1] + rd[2] + rd[3]) * 0.0078125f;
    float var2 = ex22 - mu2 * mu2;
    if (tid < 128) {
        float xn2 = (x1 - mu2) * rsqrtf(var2 + 1e-5f) * __ldg(g2 + o2) + __ldg(be2 + o2);
        g_x [g * AD + o2] = x1;
        g_xn[g * AD + o2] = xn2;
    }
}

// ===================== Kernel B: MLP (packed f32x2, weight-prefetch MLP=8) =====================
#define B_SMEM_FLOATS 14848
#define B_SMEM_BYTES  (B_SMEM_FLOATS * 4)

__global__ __launch_bounds__(NTHR, 2)
void mlp_kernel(const float* __restrict__ W1, const float* __restrict__ bb1,
                const float* __restrict__ W2, const float* __restrict__ bb2,
                float* __restrict__ out)
{
    extern __shared__ float sm[];
    float* xs   = sm;            // [16][128] residual x
    float* xnt  = sm + 2048;     // [128][20] LN2(x) transposed (16B-aligned rows)
    float* hdnT = sm + 4608;     // [512][20]
    float* yp   = sm + 4608;     // [2][16][128] overlays hdnT after sync

    const int tid = threadIdx.x;
    const size_t gbase = (size_t)blockIdx.x * TOK;

    // load + transpose
    for (int i = tid; i < TOK * AD; i += NTHR) {
        int t = i >> 7, o = i & 127;
        xs[i] = g_x [(gbase + t) * AD + o];
        xnt[o * 20 + t] = g_xn[(gbase + t) * AD + o];
    }
    __syncthreads();

    // GEMM1: hdn[t][j] = gelu( sum_o xn[t][o]*W1[o][j] + b1[j] )
    #pragma unroll
    for (int pass = 0; pass < 2; ++pass) {
        const int j = pass * 256 + tid;
        ull A0=0,A1=0,A2=0,A3=0,A4=0,A5=0,A6=0,A7=0;
        const float* w1p = W1 + j;
        for (int ob = 0; ob < 128; ob += 8) {
            float w[8];
            #pragma unroll
            for (int k = 0; k < 8; ++k) w[k] = __ldg(w1p + (ob + k) * HIDN);
            #pragma unroll
            for (int k = 0; k < 8; ++k) {
                ull wp = pack2(w[k], w[k]);
                const ulonglong2* xp = (const ulonglong2*)(xnt + (ob + k) * 20);
                ulonglong2 p0 = xp[0], p1 = xp[1], p2 = xp[2], p3 = xp[3];
                FFMA2(A0, p0.x, wp, A0); FFMA2(A1, p0.y, wp, A1);
                FFMA2(A2, p1.x, wp, A2); FFMA2(A3, p1.y, wp, A3);
                FFMA2(A4, p2.x, wp, A4); FFMA2(A5, p2.y, wp, A5);
                FFMA2(A6, p3.x, wp, A6); FFMA2(A7, p3.y, wp, A7);
            }
        }
        float bj = __ldg(bb1 + j);
        ull Av[8] = {A0,A1,A2,A3,A4,A5,A6,A7};
        #pragma unroll
        for (int q = 0; q < 8; ++q) {
            float lo, hi; unpack2(Av[q], lo, hi);
            float u0 = lo + bj, u1 = hi + bj;
            hdnT[j * 20 + 2 * q    ] = 0.5f * u0 * (1.0f + erff(u0 * 0.7071067811865476f));
            hdnT[j * 20 + 2 * q + 1] = 0.5f * u1 * (1.0f + erff(u1 * 0.7071067811865476f));
        }
    }
    __syncthreads();

    // GEMM2: y[t][o] = sum_j hdn[t][j]*W2[j][o]  (split j across thread halves)
    {
        const int o = tid & 127, jh = tid >> 7;
        ull Y0=0,Y1=0,Y2=0,Y3=0,Y4=0,Y5=0,Y6=0,Y7=0;
        const float* w2p = W2 + o;
        const int j0 = jh << 8;
        for (int jb = 0; jb < 256; jb += 8) {
            float w[8];
            #pragma unroll
            for (int k = 0; k < 8; ++k) w[k] = __ldg(w2p + (j0 + jb + k) * AD);
            #pragma unroll
            for (int k = 0; k < 8; ++k) {
                ull wp = pack2(w[k], w[k]);
                const ulonglong2* hp = (const ulonglong2*)(hdnT + (j0 + jb + k) * 20);
                ulonglong2 p0 = hp[0], p1 = hp[1], p2 = hp[2], p3 = hp[3];
                FFMA2(Y0, p0.x, wp, Y0); FFMA2(Y1, p0.y, wp, Y1);
                FFMA2(Y2, p1.x, wp, Y2); FFMA2(Y3, p1.y, wp, Y3);
                FFMA2(Y4, p2.x, wp, Y4); FFMA2(Y5, p2.y, wp, Y5);
                FFMA2(Y6, p3.x, wp, Y6); FFMA2(Y7, p3.y, wp, Y7);
            }
        }
        ull Yv[8] = {Y0,Y1,Y2,Y3,Y4,Y5,Y6,Y7};
        float yv[16];
        #pragma unroll
        for (int q = 0; q < 8; ++q) unpack2(Yv[q], yv[2 * q], yv[2 * q + 1]);
        __syncthreads();   // all reads of hdnT complete before yp overlays it
        #pragma unroll
        for (int i = 0; i < 16; ++i)
            yp[(jh * 16 + i) * 128 + o] = yv[i];
    }
    __syncthreads();

    // combine + residual + b2 + store
    {
        const int o = tid & 127, tg = tid >> 7;
        float bv = __ldg(bb2 + o);
        #pragma unroll
        for (int i = 0; i < 8; ++i) {
            int t = tg * 8 + i;
            float val = yp[t * 128 + o] + yp[(16 + t) * 128 + o] + xs[t * 128 + o] + bv;
            out[(gbase + (size_t)t) * AD + o] = val;
        }
    }
}

extern "C" void kernel_launch(void* const* d_in, const int* in_sizes, int n_in,
                              void* d_out, int out_size)
{
    const float* Q   = (const float*)d_in[0];
    const float* K   = (const float*)d_in[1];
    const float* V   = (const float*)d_in[2];
    const void*  Mk  = d_in[3];
    const float* g1  = (const float*)d_in[4];
    const float* be1 = (const float*)d_in[5];
    const float* g2  = (const float*)d_in[6];
    const float* be2 = (const float*)d_in[7];
    const float* W1  = (const float*)d_in[8];
    const float* bb1 = (const float*)d_in[9];
    const float* W2  = (const float*)d_in[10];
    const float* bb2 = (const float*)d_in[11];
    float* out = (float*)d_out;

    cudaFuncSetAttribute(attn_kernel,
                         cudaFuncAttributeMaxDynamicSharedMemorySize, A_SMEM_BYTES);
    cudaFuncSetAttribute(mlp_kernel,
                         cudaFuncAttributeMaxDynamicSharedMemorySize, B_SMEM_BYTES);

    detect_mask_kernel<<<1, NTHR>>>((const unsigned int*)Mk);

    attn_kernel<<<NTOK, NTHR, A_SMEM_BYTES>>>(Q, K, V, Mk, g1, be1, g2, be2);

    mlp_kernel<<<NTOK / TOK, NTHR, B_SMEM_BYTES>>>(W1, bb1, W2, bb2, out);

    pad_kernel<<<1, 32>>>();   // 4 launches/call: ncu -s 5 lands on attn_kernel
}

// round 10
// speedup vs baseline: 1.9544x; 1.0477x over previous
#include <cuda_runtime.h>
#include <math.h>

// Problem constants
#define NB    2
#define NRR   16384
#define MMSK  64
#define AD    128
#define HIDN  512
#define TOK   32          // tokens per MLP block
#define NTHR  256
#define NTOK  (NB * NRR)  // 32768

typedef unsigned long long ull;

__device__ float g_x [NTOK * AD];   // LN1 output (residual for MLP)
__device__ float g_xn[NTOK * AD];   // LN2 output (MLP input)

__device__ __forceinline__ float warp_sum(float v) {
    #pragma unroll
    for (int s = 16; s; s >>= 1) v += __shfl_xor_sync(0xffffffffu, v, s);
    return v;
}
__device__ __forceinline__ float warp_max(float v) {
    #pragma unroll
    for (int s = 16; s; s >>= 1) v = fmaxf(v, __shfl_xor_sync(0xffffffffu, v, s));
    return v;
}

// packed f32x2 helpers (Blackwell FFMA2 — PTX-only path)
__device__ __forceinline__ ull pack2(float lo, float hi) {
    ull r; asm("mov.b64 %0, {%1, %2};" : "=l"(r) : "f"(lo), "f"(hi)); return r;
}
__device__ __forceinline__ void unpack2(ull v, float& lo, float& hi) {
    asm("mov.b64 {%0, %1}, %2;" : "=f"(lo), "=f"(hi) : "l"(v));
}
#define FFMA2(d, a, b, c) asm("fma.rn.f32x2 %0, %1, %2, %3;" : "=l"(d) : "l"(a), "l"(b), "l"(c))

// ===================== Kernel A: attention + LN1 + LN2, one token per block =====================
// Smem floats: Ks 8192 | Vs 8192 | qs 128 | mb 64 | att 256 | ra/rb/rc/rd 4x8 | avp 256
#define A_SMEM_FLOATS 17136
#define A_SMEM_BYTES  (A_SMEM_FLOATS * 4)

__global__ __launch_bounds__(NTHR, 3)
void attn_kernel(const float* __restrict__ Q,  const float* __restrict__ K,
                 const float* __restrict__ V,  const void*  __restrict__ maskp,
                 const float* __restrict__ g1, const float* __restrict__ be1,
                 const float* __restrict__ g2, const float* __restrict__ be2)
{
    extern __shared__ float sm[];
    float* Ks  = sm;              // swizzled K tile
    float* Vs  = sm + 8192;       // swizzled V tile
    float* qs  = sm + 16384;
    float* mb  = sm + 16512;
    float* att = sm + 16576;
    float* ra  = sm + 16832;
    float* rb  = sm + 16840;
    float* rc  = sm + 16848;
    float* rd  = sm + 16856;
    float* avp = sm + 16864;

    const int tid  = threadIdx.x;
    const int wid  = tid >> 5;
    const int lane = tid & 31;
    const size_t g = (size_t)blockIdx.x;
    const int n   = (int)(g % NRR);

    // K group first, V second -> V load overlaps logits+softmax
    {
        const float4* Kg = (const float4*)(K + g * (size_t)(MMSK * AD));
        const float4* Vg = (const float4*)(V + g * (size_t)(MMSK * AD));
        #pragma unroll
        for (int r = 0; r < 8; ++r) {
            int idx = tid + r * NTHR;          // float4 index in [0,2048)
            int m = idx >> 5, c = idx & 31;
            int u = (c + m) & 31;
            unsigned ka = (unsigned)__cvta_generic_to_shared(Ks + m * 128 + u * 4);
            asm volatile("cp.async.cg.shared.global [%0], [%1], 16;" :: "r"(ka), "l"(Kg + idx));
        }
        asm volatile("cp.async.commit_group;");        // group: K
        #pragma unroll
        for (int r = 0; r < 8; ++r) {
            int idx = tid + r * NTHR;
            int m = idx >> 5, c = idx & 31;
            int u = (c + m) & 31;
            unsigned va = (unsigned)__cvta_generic_to_shared(Vs + m * 128 + u * 4);
            asm volatile("cp.async.cg.shared.global [%0], [%1], 16;" :: "r"(va), "l"(Vg + idx));
        }
        asm volatile("cp.async.commit_group;");        // group: V
        if (tid < 32) ((float4*)qs)[tid] = ((const float4*)(Q + g * AD))[tid];

        // in-block mask dtype detection: validate first 64 words of the buffer
        // (256 B — always in-bounds for byte(1MB)/word(4MB) layouts). Word mode
        // iff every word is in {0, 1, 0x3F800000}; a packed-bool buffer fails
        // this with probability 1 - 8^-64.
        int ok = 1;
        if (tid < 64) {
            unsigned v = ((const unsigned*)maskp)[tid];
            if (!(v == 0u || v == 1u || v == 0x3F800000u)) ok = 0;
        }
        int wordmode = __syncthreads_and(ok);
        if (tid < MMSK) {
            bool masked;
            if (wordmode) masked = ((const unsigned*)maskp)[(size_t)n * MMSK + tid] != 0u;
            else          masked = ((const unsigned char*)maskp)[(size_t)n * MMSK + tid] != 0;
            mb[tid] = masked ? -INFINITY : 0.0f;
        }
        asm volatile("cp.async.wait_group 1;");        // K complete (V may be in flight)
        __syncthreads();                                                // BAR 1
    }

    // logits + softmax: warp w = head w (warps 0-3), lane owns m=lane and m=lane+32.
    if (wid < 4) {
        const int h = wid;
        const int m0 = lane, m1 = lane + 32;
        float acc0 = 0.f, acc1 = 0.f;
        #pragma unroll
        for (int j4 = 0; j4 < 8; ++j4) {
            int c = 8 * h + j4;
            float4 q4 = *(const float4*)(qs + c * 4);
            int u0 = (c + m0) & 31;
            float4 k0 = *(const float4*)(Ks + m0 * 128 + u0 * 4);
            acc0 = fmaf(k0.x, q4.x, acc0); acc0 = fmaf(k0.y, q4.y, acc0);
            acc0 = fmaf(k0.z, q4.z, acc0); acc0 = fmaf(k0.w, q4.w, acc0);
            int u1 = (c + m1) & 31;
            float4 k1 = *(const float4*)(Ks + m1 * 128 + u1 * 4);
            acc1 = fmaf(k1.x, q4.x, acc1); acc1 = fmaf(k1.y, q4.y, acc1);
            acc1 = fmaf(k1.z, q4.z, acc1); acc1 = fmaf(k1.w, q4.w, acc1);
        }
        float l0 = acc0 * 0.17677669529663689f + mb[m0];   // 1/sqrt(32)
        float l1 = acc1 * 0.17677669529663689f + mb[m1];
        float wm = warp_max(fmaxf(l0, l1));
        float p0 = __expf(l0 - wm), p1 = __expf(l1 - wm);
        float s  = warp_sum(p0 + p1);
        float inv = 1.0f / s;
        att[h * 64 + m0] = p0 * inv;
        att[h * 64 + m1] = p1 * inv;
    }
    asm volatile("cp.async.wait_group 0;");            // V complete
    __syncthreads();                                                    // BAR 2

    // AV: thread (o, half) sums 32 m; bank = (o + 4m) mod 32 -> conflict-free
    {
        int o = tid & 127, half = tid >> 7;
        int hh = o >> 5;
        const float* ah = att + hh * 64 + half * 32;
        float s = 0.f;
        #pragma unroll
        for (int i2 = 0; i2 < 32; ++i2) {
            int mm = half * 32 + i2;
            int u = (((o >> 2) + mm) & 31);
            s = fmaf(ah[i2], Vs[mm * 128 + u * 4 + (o & 3)], s);
        }
        avp[tid] = s;
    }
    __syncthreads();                                                    // BAR 3

    // residual + LN1 + LN2 via single-pass E[x^2]-E[x]^2
    const int o2 = tid & 127;
    float xv = 0.f;
    if (tid < 128) xv = qs[o2] + avp[o2] + avp[128 + o2];

    {
        float s1 = warp_sum((tid < 128) ? xv : 0.f);
        float s2 = warp_sum((tid < 128) ? xv * xv : 0.f);
        if (lane == 0 && wid < 4) { ra[wid] = s1; rb[wid] = s2; }
    }
    __syncthreads();                                                    // BAR 4
    float mu  = (ra[0] + ra[1] + ra[2] + ra[3]) * 0.0078125f;
    float ex2 = (rb[0] + rb[1] + rb[2] + rb[3]) * 0.0078125f;
    float var = ex2 - mu * mu;
    float x1 = 0.f;
    if (tid < 128)
        x1 = (xv - mu) * rsqrtf(var + 1e-5f) * __ldg(g1 + o2) + __ldg(be1 + o2);

    {
        float s1 = warp_sum((tid < 128) ? x1 : 0.f);
        float s2 = warp_sum((tid < 128) ? x1 * x1 : 0.f);
        if (lane == 0 && wid < 4) { rc[wid] = s1; rd[wid] = s2; }
    }
    __syncthreads();                                                    // BAR 5
    float mu2  = (rc[0] + rc[1] + rc[2] + rc[3]) * 0.0078125f;
    float ex22 = (rd[0] + rd[1] + rd[2] + rd[3]) * 0.0078125f;
    float var2 = ex22 - mu2 * mu2;
    if (tid < 128) {
        float xn2 = (x1 - mu2) * rsqrtf(var2 + 1e-5f) * __ldg(g2 + o2) + __ldg(be2 + o2);
        g_x [g * AD + o2] = x1;
        g_xn[g * AD + o2] = xn2;
    }
}

// ===================== Kernel B: MLP, 32 tokens/block (packed f32x2, prefetch-8) =====================
// Smem floats: xs [32][128]=4096 | xnt [128][36]=4608 | hdnT [512][36]=18432  -> 27136
#define B_SMEM_FLOATS 27136
#define B_SMEM_BYTES  (B_SMEM_FLOATS * 4)

__global__ __launch_bounds__(NTHR, 2)
void mlp_kernel(const float* __restrict__ W1, const float* __restrict__ bb1,
                const float* __restrict__ W2, const float* __restrict__ bb2,
                float* __restrict__ out)
{
    extern __shared__ float sm[];
    float* xs   = sm;            // [32][128] residual x
    float* xnt  = sm + 4096;     // [128][36] LN2(x) transposed (rows 16B-aligned)
    float* hdnT = sm + 8704;     // [512][36]

    const int tid = threadIdx.x;
    const size_t gbase = (size_t)blockIdx.x * TOK;

    // load + transpose
    for (int i = tid; i < TOK * AD; i += NTHR) {
        int t = i >> 7, o = i & 127;
        xs[i] = g_x [(gbase + t) * AD + o];
        xnt[o * 36 + t] = g_xn[(gbase + t) * AD + o];
    }
    __syncthreads();

    // GEMM1: hdn[t][j] = gelu( sum_o xn[t][o]*W1[o][j] + b1[j] ), 32 tokens = 16 f32x2 accs
    #pragma unroll
    for (int pass = 0; pass < 2; ++pass) {
        const int j = pass * 256 + tid;
        ull A0=0,A1=0,A2=0,A3=0,A4=0,A5=0,A6=0,A7=0;
        ull A8=0,A9=0,A10=0,A11=0,A12=0,A13=0,A14=0,A15=0;
        const float* w1p = W1 + j;
        for (int ob = 0; ob < 128; ob += 8) {
            float w[8];
            #pragma unroll
            for (int k = 0; k < 8; ++k) w[k] = __ldg(w1p + (ob + k) * HIDN);
            #pragma unroll
            for (int k = 0; k < 8; ++k) {
                ull wp = pack2(w[k], w[k]);
                const ulonglong2* xp = (const ulonglong2*)(xnt + (ob + k) * 36);
                ulonglong2 q0 = xp[0], q1 = xp[1], q2 = xp[2], q3 = xp[3];
                ulonglong2 q4 = xp[4], q5 = xp[5], q6 = xp[6], q7 = xp[7];
                FFMA2(A0,  q0.x, wp, A0);  FFMA2(A1,  q0.y, wp, A1);
                FFMA2(A2,  q1.x, wp, A2);  FFMA2(A3,  q1.y, wp, A3);
                FFMA2(A4,  q2.x, wp, A4);  FFMA2(A5,  q2.y, wp, A5);
                FFMA2(A6,  q3.x, wp, A6);  FFMA2(A7,  q3.y, wp, A7);
                FFMA2(A8,  q4.x, wp, A8);  FFMA2(A9,  q4.y, wp, A9);
                FFMA2(A10, q5.x, wp, A10); FFMA2(A11, q5.y, wp, A11);
                FFMA2(A12, q6.x, wp, A12); FFMA2(A13, q6.y, wp, A13);
                FFMA2(A14, q7.x, wp, A14); FFMA2(A15, q7.y, wp, A15);
            }
        }
        float bj = __ldg(bb1 + j);
        ull Av[16] = {A0,A1,A2,A3,A4,A5,A6,A7,A8,A9,A10,A11,A12,A13,A14,A15};
        #pragma unroll
        for (int q = 0; q < 16; ++q) {
            float lo, hi; unpack2(Av[q], lo, hi);
            float u0 = lo + bj, u1 = hi + bj;
            hdnT[j * 36 + 2 * q    ] = 0.5f * u0 * (1.0f + erff(u0 * 0.7071067811865476f));
            hdnT[j * 36 + 2 * q + 1] = 0.5f * u1 * (1.0f + erff(u1 * 0.7071067811865476f));
        }
    }
    __syncthreads();

    // GEMM2: thread (o, token-half) sums ALL 512 j -> no partial combine, direct store
    {
        const int o = tid & 127, th = tid >> 7;
        ull Y0=0,Y1=0,Y2=0,Y3=0,Y4=0,Y5=0,Y6=0,Y7=0;
        const float* w2p = W2 + o;
        const int toff = th * 16;   // 16 tokens = 8 f32x2
        for (int jb = 0; jb < HIDN; jb += 8) {
            float w[8];
            #pragma unroll
            for (int k = 0; k < 8; ++k) w[k] = __ldg(w2p + (jb + k) * AD);
            #pragma unroll
            for (int k = 0; k < 8; ++k) {
                ull wp = pack2(w[k], w[k]);
                const ulonglong2* hp = (const ulonglong2*)(hdnT + (jb + k) * 36 + toff);
                ulonglong2 q0 = hp[0], q1 = hp[1], q2 = hp[2], q3 = hp[3];
                FFMA2(Y0, q0.x, wp, Y0); FFMA2(Y1, q0.y, wp, Y1);
                FFMA2(Y2, q1.x, wp, Y2); FFMA2(Y3, q1.y, wp, Y3);
                FFMA2(Y4, q2.x, wp, Y4); FFMA2(Y5, q2.y, wp, Y5);
                FFMA2(Y6, q3.x, wp, Y6); FFMA2(Y7, q3.y, wp, Y7);
            }
        }
        ull Yv[8] = {Y0,Y1,Y2,Y3,Y4,Y5,Y6,Y7};
        float yv[16];
        #pragma unroll
        for (int q = 0; q < 8; ++q) unpack2(Yv[q], yv[2 * q], yv[2 * q + 1]);
        float bv = __ldg(bb2 + o);
        #pragma unroll
        for (int i = 0; i < 16; ++i) {
            int t = toff + i;
            out[(gbase + (size_t)t) * AD + o] = yv[i] + xs[t * 128 + o] + bv;
        }
    }
}

extern "C" void kernel_launch(void* const* d_in, const int* in_sizes, int n_in,
                              void* d_out, int out_size)
{
    const float* Q   = (const float*)d_in[0];
    const float* K   = (const float*)d_in[1];
    const float* V   = (const float*)d_in[2];
    const void*  Mk  = d_in[3];
    const float* g1  = (const float*)d_in[4];
    const float* be1 = (const float*)d_in[5];
    const float* g2  = (const float*)d_in[6];
    const float* be2 = (const float*)d_in[7];
    const float* W1  = (const float*)d_in[8];
    const float* bb1 = (const float*)d_in[9];
    const float* W2  = (const float*)d_in[10];
    const float* bb2 = (const float*)d_in[11];
    float* out = (float*)d_out;

    cudaFuncSetAttribute(attn_kernel,
                         cudaFuncAttributeMaxDynamicSharedMemorySize, A_SMEM_BYTES);
    cudaFuncSetAttribute(mlp_kernel,
                         cudaFuncAttributeMaxDynamicSharedMemorySize, B_SMEM_BYTES);

    attn_kernel<<<NTOK, NTHR, A_SMEM_BYTES>>>(Q, K, V, Mk, g1, be1, g2, be2);

    mlp_kernel<<<NTOK / TOK, NTHR, B_SMEM_BYTES>>>(W1, bb1, W2, bb2, out);
    // 2 launches/call: profiled launch index is odd -> ncu deterministically
    // captures mlp_kernel this round.
}

// round 11
// speedup vs baseline: 2.1909x; 1.1210x over previous
#include <cuda_runtime.h>
#include <math.h>

// Problem constants
#define NB    2
#define NRR   16384
#define MMSK  64
#define AD    128
#define HIDN  512
#define TOK   32          // tokens per MLP block
#define NTHR  256
#define NTOK  (NB * NRR)  // 32768

typedef unsigned long long ull;

__device__ float g_x [NTOK * AD];   // LN1 output (residual for MLP)
__device__ float g_xn[NTOK * AD];   // LN2 output (MLP input)

__device__ __forceinline__ float warp_sum(float v) {
    #pragma unroll
    for (int s = 16; s; s >>= 1) v += __shfl_xor_sync(0xffffffffu, v, s);
    return v;
}
__device__ __forceinline__ float warp_max(float v) {
    #pragma unroll
    for (int s = 16; s; s >>= 1) v = fmaxf(v, __shfl_xor_sync(0xffffffffu, v, s));
    return v;
}

// packed f32x2 helpers (Blackwell FFMA2 — PTX-only path)
__device__ __forceinline__ ull pack2(float lo, float hi) {
    ull r; asm("mov.b64 %0, {%1, %2};" : "=l"(r) : "f"(lo), "f"(hi)); return r;
}
__device__ __forceinline__ void unpack2(ull v, float& lo, float& hi) {
    asm("mov.b64 {%0, %1}, %2;" : "=f"(lo), "=f"(hi) : "l"(v));
}
#define FFMA2(d, a, b, c) asm("fma.rn.f32x2 %0, %1, %2, %3;" : "=l"(d) : "l"(a), "l"(b), "l"(c))

__device__ __forceinline__ float gelu_f(float u) {
    return 0.5f * u * (1.0f + erff(u * 0.7071067811865476f));
}

// ===================== Kernel A: attention + LN1 + LN2, one token per block =====================
// Smem floats: Ks 8192 | Vs 8192 | qs 128 | mb 64 | att 256 | ra/rb/rc/rd 4x8 | avp 256
#define A_SMEM_FLOATS 17136
#define A_SMEM_BYTES  (A_SMEM_FLOATS * 4)

__global__ __launch_bounds__(NTHR, 3)
void attn_kernel(const float* __restrict__ Q,  const float* __restrict__ K,
                 const float* __restrict__ V,  const void*  __restrict__ maskp,
                 const float* __restrict__ g1, const float* __restrict__ be1,
                 const float* __restrict__ g2, const float* __restrict__ be2)
{
    extern __shared__ float sm[];
    float* Ks  = sm;              // swizzled K tile
    float* Vs  = sm + 8192;       // swizzled V tile
    float* qs  = sm + 16384;
    float* mb  = sm + 16512;
    float* att = sm + 16576;
    float* ra  = sm + 16832;
    float* rb  = sm + 16840;
    float* rc  = sm + 16848;
    float* rd  = sm + 16856;
    float* avp = sm + 16864;

    const int tid  = threadIdx.x;
    const int wid  = tid >> 5;
    const int lane = tid & 31;
    const size_t g = (size_t)blockIdx.x;
    const int n   = (int)(g % NRR);

    // K group first, V second -> V load overlaps logits+softmax
    {
        const float4* Kg = (const float4*)(K + g * (size_t)(MMSK * AD));
        const float4* Vg = (const float4*)(V + g * (size_t)(MMSK * AD));
        #pragma unroll
        for (int r = 0; r < 8; ++r) {
            int idx = tid + r * NTHR;          // float4 index in [0,2048)
            int m = idx >> 5, c = idx & 31;
            int u = (c + m) & 31;
            unsigned ka = (unsigned)__cvta_generic_to_shared(Ks + m * 128 + u * 4);
            asm volatile("cp.async.cg.shared.global [%0], [%1], 16;" :: "r"(ka), "l"(Kg + idx));
        }
        asm volatile("cp.async.commit_group;");        // group: K
        #pragma unroll
        for (int r = 0; r < 8; ++r) {
            int idx = tid + r * NTHR;
            int m = idx >> 5, c = idx & 31;
            int u = (c + m) & 31;
            unsigned va = (unsigned)__cvta_generic_to_shared(Vs + m * 128 + u * 4);
            asm volatile("cp.async.cg.shared.global [%0], [%1], 16;" :: "r"(va), "l"(Vg + idx));
        }
        asm volatile("cp.async.commit_group;");        // group: V
        if (tid < 32) ((float4*)qs)[tid] = ((const float4*)(Q + g * AD))[tid];

        // in-block mask dtype detection (first 64 words — in-bounds either dtype)
        int ok = 1;
        if (tid < 64) {
            unsigned v = ((const unsigned*)maskp)[tid];
            if (!(v == 0u || v == 1u || v == 0x3F800000u)) ok = 0;
        }
        int wordmode = __syncthreads_and(ok);
        if (tid < MMSK) {
            bool masked;
            if (wordmode) masked = ((const unsigned*)maskp)[(size_t)n * MMSK + tid] != 0u;
            else          masked = ((const unsigned char*)maskp)[(size_t)n * MMSK + tid] != 0;
            mb[tid] = masked ? -INFINITY : 0.0f;
        }
        asm volatile("cp.async.wait_group 1;");        // K complete (V may be in flight)
        __syncthreads();                                                // BAR 1
    }

    // logits + softmax: warp w = head w (warps 0-3), lane owns m=lane and m=lane+32.
    if (wid < 4) {
        const int h = wid;
        const int m0 = lane, m1 = lane + 32;
        float acc0 = 0.f, acc1 = 0.f;
        #pragma unroll
        for (int j4 = 0; j4 < 8; ++j4) {
            int c = 8 * h + j4;
            float4 q4 = *(const float4*)(qs + c * 4);
            int u0 = (c + m0) & 31;
            float4 k0 = *(const float4*)(Ks + m0 * 128 + u0 * 4);
            acc0 = fmaf(k0.x, q4.x, acc0); acc0 = fmaf(k0.y, q4.y, acc0);
            acc0 = fmaf(k0.z, q4.z, acc0); acc0 = fmaf(k0.w, q4.w, acc0);
            int u1 = (c + m1) & 31;
            float4 k1 = *(const float4*)(Ks + m1 * 128 + u1 * 4);
            acc1 = fmaf(k1.x, q4.x, acc1); acc1 = fmaf(k1.y, q4.y, acc1);
            acc1 = fmaf(k1.z, q4.z, acc1); acc1 = fmaf(k1.w, q4.w, acc1);
        }
        float l0 = acc0 * 0.17677669529663689f + mb[m0];   // 1/sqrt(32)
        float l1 = acc1 * 0.17677669529663689f + mb[m1];
        float wm = warp_max(fmaxf(l0, l1));
        float p0 = __expf(l0 - wm), p1 = __expf(l1 - wm);
        float s  = warp_sum(p0 + p1);
        float inv = 1.0f / s;
        att[h * 64 + m0] = p0 * inv;
        att[h * 64 + m1] = p1 * inv;
    }
    asm volatile("cp.async.wait_group 0;");            // V complete
    __syncthreads();                                                    // BAR 2

    // AV: thread (o, half) sums 32 m; bank = (o + 4m) mod 32 -> conflict-free
    {
        int o = tid & 127, half = tid >> 7;
        int hh = o >> 5;
        const float* ah = att + hh * 64 + half * 32;
        float s = 0.f;
        #pragma unroll
        for (int i2 = 0; i2 < 32; ++i2) {
            int mm = half * 32 + i2;
            int u = (((o >> 2) + mm) & 31);
            s = fmaf(ah[i2], Vs[mm * 128 + u * 4 + (o & 3)], s);
        }
        avp[tid] = s;
    }
    __syncthreads();                                                    // BAR 3

    // residual + LN1 + LN2 via single-pass E[x^2]-E[x]^2
    const int o2 = tid & 127;
    float xv = 0.f;
    if (tid < 128) xv = qs[o2] + avp[o2] + avp[128 + o2];

    {
        float s1 = warp_sum((tid < 128) ? xv : 0.f);
        float s2 = warp_sum((tid < 128) ? xv * xv : 0.f);
        if (lane == 0 && wid < 4) { ra[wid] = s1; rb[wid] = s2; }
    }
    __syncthreads();                                                    // BAR 4
    float mu  = (ra[0] + ra[1] + ra[2] + ra[3]) * 0.0078125f;
    float ex2 = (rb[0] + rb[1] + rb[2] + rb[3]) * 0.0078125f;
    float var = ex2 - mu * mu;
    float x1 = 0.f;
    if (tid < 128)
        x1 = (xv - mu) * rsqrtf(var + 1e-5f) * __ldg(g1 + o2) + __ldg(be1 + o2);

    {
        float s1 = warp_sum((tid < 128) ? x1 : 0.f);
        float s2 = warp_sum((tid < 128) ? x1 * x1 : 0.f);
        if (lane == 0 && wid < 4) { rc[wid] = s1; rd[wid] = s2; }
    }
    __syncthreads();                                                    // BAR 5
    float mu2  = (rc[0] + rc[1] + rc[2] + rc[3]) * 0.0078125f;
    float ex22 = (rd[0] + rd[1] + rd[2] + rd[3]) * 0.0078125f;
    float var2 = ex22 - mu2 * mu2;
    if (tid < 128) {
        float xn2 = (x1 - mu2) * rsqrtf(var2 + 1e-5f) * __ldg(g2 + o2) + __ldg(be2 + o2);
        g_x [g * AD + o2] = x1;
        g_xn[g * AD + o2] = xn2;
    }
}

// ===================== Kernel B: MLP, 32 tokens/block, register-blocked outputs =====================
// Smem floats: xs [32][128]=4096 | xnt [128][36]=4608 | hdnT [512][36]=18432  -> 27136
#define B_SMEM_FLOATS 27136
#define B_SMEM_BYTES  (B_SMEM_FLOATS * 4)

__global__ __launch_bounds__(NTHR, 2)
void mlp_kernel(const float* __restrict__ W1, const float* __restrict__ bb1,
                const float* __restrict__ W2, const float* __restrict__ bb2,
                float* __restrict__ out)
{
    extern __shared__ float sm[];
    float* xs   = sm;            // [32][128] residual x
    float* xnt  = sm + 4096;     // [128][36] LN2(x) transposed (rows 16B-aligned)
    float* hdnT = sm + 8704;     // [512][36]

    const int tid = threadIdx.x;
    const size_t gbase = (size_t)blockIdx.x * TOK;

    // load + transpose
    for (int i = tid; i < TOK * AD; i += NTHR) {
        int t = i >> 7, o = i & 127;
        xs[i] = g_x [(gbase + t) * AD + o];
        xnt[o * 36 + t] = g_xn[(gbase + t) * AD + o];
    }
    __syncthreads();

    // GEMM1: thread owns j-pair (j, j+256); two passes over 16-token halves.
    // Each xnt row-read (4 LDS.128) feeds 16 FFMA2 (2 j-columns).
    {
        const int j = tid;
        const float* w1a = W1 + j;
        const float* w1b = W1 + j + 256;
        const float bja = __ldg(bb1 + j);
        const float bjb = __ldg(bb1 + j + 256);
        #pragma unroll
        for (int th = 0; th < 2; ++th) {
            const int toff = th * 16;
            ull A0=0,A1=0,A2=0,A3=0,A4=0,A5=0,A6=0,A7=0;      // j
            ull B0=0,B1=0,B2=0,B3=0,B4=0,B5=0,B6=0,B7=0;      // j+256
            for (int ob = 0; ob < 128; ob += 4) {
                float wa[4], wb[4];
                #pragma unroll
                for (int k = 0; k < 4; ++k) {
                    wa[k] = __ldg(w1a + (ob + k) * HIDN);
                    wb[k] = __ldg(w1b + (ob + k) * HIDN);
                }
                #pragma unroll
                for (int k = 0; k < 4; ++k) {
                    ull wpa = pack2(wa[k], wa[k]);
                    ull wpb = pack2(wb[k], wb[k]);
                    const ulonglong2* xp = (const ulonglong2*)(xnt + (ob + k) * 36 + toff);
                    ulonglong2 q0 = xp[0], q1 = xp[1];
                    FFMA2(A0, q0.x, wpa, A0); FFMA2(A1, q0.y, wpa, A1);
                    FFMA2(A2, q1.x, wpa, A2); FFMA2(A3, q1.y, wpa, A3);
                    FFMA2(B0, q0.x, wpb, B0); FFMA2(B1, q0.y, wpb, B1);
                    FFMA2(B2, q1.x, wpb, B2); FFMA2(B3, q1.y, wpb, B3);
                    const ulonglong2* xp2 = (const ulonglong2*)(xnt + (ob + k) * 36 + toff + 8);
                    ulonglong2 q2 = xp2[0], q3 = xp2[1];
                    FFMA2(A4, q2.x, wpa, A4); FFMA2(A5, q2.y, wpa, A5);
                    FFMA2(A6, q3.x, wpa, A6); FFMA2(A7, q3.y, wpa, A7);
                    FFMA2(B4, q2.x, wpb, B4); FFMA2(B5, q2.y, wpb, B5);
                    FFMA2(B6, q3.x, wpb, B6); FFMA2(B7, q3.y, wpb, B7);
                }
            }
            ull Av[8] = {A0,A1,A2,A3,A4,A5,A6,A7};
            ull Bv[8] = {B0,B1,B2,B3,B4,B5,B6,B7};
            #pragma unroll
            for (int q = 0; q < 8; ++q) {
                float lo, hi;
                unpack2(Av[q], lo, hi);
                hdnT[j * 36 + toff + 2 * q    ] = gelu_f(lo + bja);
                hdnT[j * 36 + toff + 2 * q + 1] = gelu_f(hi + bja);
                unpack2(Bv[q], lo, hi);
                hdnT[(j + 256) * 36 + toff + 2 * q    ] = gelu_f(lo + bjb);
                hdnT[(j + 256) * 36 + toff + 2 * q + 1] = gelu_f(hi + bjb);
            }
        }
    }
    __syncthreads();

    // GEMM2: thread owns o-pair (2op, 2op+1) and an 8-token group; sums ALL 512 j.
    // Each hdnT row-read (2 LDS.128) feeds 8 FFMA2; weights via one LDG.64 per j.
    {
        const int op = tid & 63;           // o = 2op, 2op+1
        const int tg = tid >> 6;           // 0..3 (uniform per warp-pair)
        const int toff = tg * 8;           // 8 tokens = 4 f32x2
        ull Ya0=0,Ya1=0,Ya2=0,Ya3=0;       // o = 2op
        ull Yb0=0,Yb1=0,Yb2=0,Yb3=0;       // o = 2op+1
        for (int jb = 0; jb < HIDN; jb += 8) {
            float2 w[8];
            #pragma unroll
            for (int k = 0; k < 8; ++k)
                w[k] = __ldg((const float2*)(W2 + (size_t)(jb + k) * AD) + op);
            #pragma unroll
            for (int k = 0; k < 8; ++k) {
                ull wpa = pack2(w[k].x, w[k].x);
                ull wpb = pack2(w[k].y, w[k].y);
                const ulonglong2* hp = (const ulonglong2*)(hdnT + (jb + k) * 36 + toff);
                ulonglong2 q0 = hp[0], q1 = hp[1];
                FFMA2(Ya0, q0.x, wpa, Ya0); FFMA2(Ya1, q0.y, wpa, Ya1);
                FFMA2(Ya2, q1.x, wpa, Ya2); FFMA2(Ya3, q1.y, wpa, Ya3);
                FFMA2(Yb0, q0.x, wpb, Yb0); FFMA2(Yb1, q0.y, wpb, Yb1);
                FFMA2(Yb2, q1.x, wpb, Yb2); FFMA2(Yb3, q1.y, wpb, Yb3);
            }
        }
        ull Yav[4] = {Ya0,Ya1,Ya2,Ya3};
        ull Ybv[4] = {Yb0,Yb1,Yb2,Yb3};
        float ya[8], yb[8];
        #pragma unroll
        for (int q = 0; q < 4; ++q) {
            unpack2(Yav[q], ya[2 * q], ya[2 * q + 1]);
            unpack2(Ybv[q], yb[2 * q], yb[2 * q + 1]);
        }
        float2 bv = __ldg((const float2*)bb2 + op);
        #pragma unroll
        for (int i = 0; i < 8; ++i) {
            int t = toff + i;
            float2 xr = *(const float2*)(xs + t * 128 + 2 * op);
            float2 res;
            res.x = ya[i] + xr.x + bv.x;
            res.y = yb[i] + xr.y + bv.y;
            *(float2*)(out + (gbase + (size_t)t) * AD + 2 * op) = res;
        }
    }
}

extern "C" void kernel_launch(void* const* d_in, const int* in_sizes, int n_in,
                              void* d_out, int out_size)
{
    const float* Q   = (const float*)d_in[0];
    const float* K   = (const float*)d_in[1];
    const float* V   = (const float*)d_in[2];
    const void*  Mk  = d_in[3];
    const float* g1  = (const float*)d_in[4];
    const float* be1 = (const float*)d_in[5];
    const float* g2  = (const float*)d_in[6];
    const float* be2 = (const float*)d_in[7];
    const float* W1  = (const float*)d_in[8];
    const float* bb1 = (const float*)d_in[9];
    const float* W2  = (const float*)d_in[10];
    const float* bb2 = (const float*)d_in[11];
    float* out = (float*)d_out;

    cudaFuncSetAttribute(attn_kernel,
                         cudaFuncAttributeMaxDynamicSharedMemorySize, A_SMEM_BYTES);
    cudaFuncSetAttribute(mlp_kernel,
                         cudaFuncAttributeMaxDynamicSharedMemorySize, B_SMEM_BYTES);

    attn_kernel<<<NTOK, NTHR, A_SMEM_BYTES>>>(Q, K, V, Mk, g1, be1, g2, be2);

    mlp_kernel<<<NTOK / TOK, NTHR, B_SMEM_BYTES>>>(W1, bb1, W2, bb2, out);
    // 2 launches/call: odd profiled index -> ncu captures mlp_kernel.
}